// round 1
// baseline (speedup 1.0000x reference)
#include <cuda_runtime.h>
#include <math.h>

#define TT     2048
#define HH     16
#define DQK    192
#define DNOPE  128
#define DROPE  64
#define DLORA  512
#define DV     128
#define ATT_SCALE 0.07216878364870323f   // 1/sqrt(192)

// Scratch (static __device__ — allocation rules forbid cudaMalloc)
__device__ float g_k[HH * TT * DQK];   // (h, t, 192): k_nope | k_pe
__device__ float g_v[HH * TT * DV];    // (h, t, 128): kc @ w_uv[h]

// ---------------------------------------------------------------------------
// Kernel 1: K_nope = kc (2048x512) @ w_kv_b[:, h*256 : h*256+128] -> g_k[..,0:128]
// 64x64 tile, 16-deep k-step, 256 threads, 4x4 micro-tile
// ---------------------------------------------------------------------------
__global__ __launch_bounds__(256) void knope_kernel(const float* __restrict__ kc,
                                                    const float* __restrict__ wkv) {
    __shared__ float As[16][68];
    __shared__ float Bs[16][68];
    const int tid = threadIdx.x;
    const int m0 = blockIdx.y * 64;
    const int n0 = blockIdx.x * 64;          // n over H*128; h constant per tile
    const int h = n0 >> 7;
    const int dbase = n0 & 127;
    const int tx = tid & 15, ty = tid >> 4;
    const int am = tid >> 2, ak4 = (tid & 3) * 4;

    float acc[4][4];
#pragma unroll
    for (int i = 0; i < 4; i++)
#pragma unroll
        for (int j = 0; j < 4; j++) acc[i][j] = 0.f;

    for (int k0 = 0; k0 < DLORA; k0 += 16) {
        float4 av = *(const float4*)&kc[(m0 + am) * DLORA + k0 + ak4];
        As[ak4 + 0][am] = av.x;
        As[ak4 + 1][am] = av.y;
        As[ak4 + 2][am] = av.z;
        As[ak4 + 3][am] = av.w;
#pragma unroll
        for (int i = 0; i < 4; i++) {
            int lin = tid + i * 256;
            int kk = lin >> 6, n = lin & 63;
            Bs[kk][n] = wkv[(k0 + kk) * (HH * 256) + h * 256 + dbase + n];
        }
        __syncthreads();
#pragma unroll
        for (int kk = 0; kk < 16; kk++) {
            float4 a = *(const float4*)&As[kk][ty * 4];
            float4 b = *(const float4*)&Bs[kk][tx * 4];
            acc[0][0] += a.x * b.x; acc[0][1] += a.x * b.y; acc[0][2] += a.x * b.z; acc[0][3] += a.x * b.w;
            acc[1][0] += a.y * b.x; acc[1][1] += a.y * b.y; acc[1][2] += a.y * b.z; acc[1][3] += a.y * b.w;
            acc[2][0] += a.z * b.x; acc[2][1] += a.z * b.y; acc[2][2] += a.z * b.z; acc[2][3] += a.z * b.w;
            acc[3][0] += a.w * b.x; acc[3][1] += a.w * b.y; acc[3][2] += a.w * b.z; acc[3][3] += a.w * b.w;
        }
        __syncthreads();
    }
#pragma unroll
    for (int i = 0; i < 4; i++) {
        float4 o = make_float4(acc[i][0], acc[i][1], acc[i][2], acc[i][3]);
        *(float4*)&g_k[(h * TT + m0 + ty * 4 + i) * DQK + dbase + tx * 4] = o;
    }
}

// ---------------------------------------------------------------------------
// Kernel 2: broadcast k_pe into g_k[h][t][128:192]
// ---------------------------------------------------------------------------
__global__ __launch_bounds__(256) void pefill_kernel(const float* __restrict__ kpe) {
    int idx = blockIdx.x * 256 + threadIdx.x;
    if (idx >= HH * TT * DROPE) return;
    int r = idx & 63;
    int t = (idx >> 6) & (TT - 1);
    int h = idx >> 17;
    g_k[(h * TT + t) * DQK + DNOPE + r] = kpe[t * DROPE + r];
}

// ---------------------------------------------------------------------------
// Kernel 3: g_v[h] = kc (2048x512) @ w_uv[h] (512x128)
// ---------------------------------------------------------------------------
__global__ __launch_bounds__(256) void vbuild_kernel(const float* __restrict__ kc,
                                                     const float* __restrict__ wuv) {
    __shared__ float As[16][68];
    __shared__ float Bs[16][68];
    const int tid = threadIdx.x;
    const int m0 = blockIdx.y * 64;
    const int n0 = blockIdx.x * 64;          // 0 or 64 within DV=128
    const int h = blockIdx.z;
    const int tx = tid & 15, ty = tid >> 4;
    const int am = tid >> 2, ak4 = (tid & 3) * 4;
    const float* wh = wuv + (size_t)h * DLORA * DV;

    float acc[4][4];
#pragma unroll
    for (int i = 0; i < 4; i++)
#pragma unroll
        for (int j = 0; j < 4; j++) acc[i][j] = 0.f;

    for (int k0 = 0; k0 < DLORA; k0 += 16) {
        float4 av = *(const float4*)&kc[(m0 + am) * DLORA + k0 + ak4];
        As[ak4 + 0][am] = av.x;
        As[ak4 + 1][am] = av.y;
        As[ak4 + 2][am] = av.z;
        As[ak4 + 3][am] = av.w;
#pragma unroll
        for (int i = 0; i < 4; i++) {
            int lin = tid + i * 256;
            int kk = lin >> 6, n = lin & 63;
            Bs[kk][n] = wh[(k0 + kk) * DV + n0 + n];
        }
        __syncthreads();
#pragma unroll
        for (int kk = 0; kk < 16; kk++) {
            float4 a = *(const float4*)&As[kk][ty * 4];
            float4 b = *(const float4*)&Bs[kk][tx * 4];
            acc[0][0] += a.x * b.x; acc[0][1] += a.x * b.y; acc[0][2] += a.x * b.z; acc[0][3] += a.x * b.w;
            acc[1][0] += a.y * b.x; acc[1][1] += a.y * b.y; acc[1][2] += a.y * b.z; acc[1][3] += a.y * b.w;
            acc[2][0] += a.z * b.x; acc[2][1] += a.z * b.y; acc[2][2] += a.z * b.z; acc[2][3] += a.z * b.w;
            acc[3][0] += a.w * b.x; acc[3][1] += a.w * b.y; acc[3][2] += a.w * b.z; acc[3][3] += a.w * b.w;
        }
        __syncthreads();
    }
#pragma unroll
    for (int i = 0; i < 4; i++) {
        float4 o = make_float4(acc[i][0], acc[i][1], acc[i][2], acc[i][3]);
        *(float4*)&g_v[(h * TT + m0 + ty * 4 + i) * DV + n0 + tx * 4] = o;
    }
}

// ---------------------------------------------------------------------------
// Kernel 4: causal flash attention, 64 q-rows x 64 k-rows per iter, d_v = 128
// out[t, h*128+v] = softmax_s(q . k / sqrt(192)) @ g_v[h]
// ---------------------------------------------------------------------------
#define QP 193   // odd stride: conflict-free strided row reads
#define SP 65
#define FLASH_SMEM_FLOATS (2 * 64 * QP + 64 * DV + 64 * SP)

__global__ __launch_bounds__(256, 1) void flash_kernel(const float* __restrict__ q,
                                                       float* __restrict__ out) {
    extern __shared__ float sm[];
    float* sQ = sm;                      // 64 x QP
    float* sK = sQ + 64 * QP;            // 64 x QP
    float* sV = sK + 64 * QP;            // 64 x 128
    float* sS = sV + 64 * DV;            // 64 x SP

    const int tid = threadIdx.x;
    const int h = blockIdx.y;
    const int qb = (gridDim.x - 1) - blockIdx.x;   // heavy blocks launch first
    const int t0 = qb * 64;

    // load Q tile (64 x 192)
#pragma unroll
    for (int i = 0; i < 12; i++) {
        int idx4 = tid + i * 256;
        int r = idx4 / 48, d4 = idx4 % 48;
        float4 v = *(const float4*)&q[(size_t)(t0 + r) * (HH * DQK) + h * DQK + d4 * 4];
        sQ[r * QP + d4 * 4 + 0] = v.x;
        sQ[r * QP + d4 * 4 + 1] = v.y;
        sQ[r * QP + d4 * 4 + 2] = v.z;
        sQ[r * QP + d4 * 4 + 3] = v.w;
    }

    const int tx = tid & 15, ty = tid >> 4;   // S-compute: rows ty*4+i, cols tx+16j
    const int pr = tid >> 2, pc = tid & 3;    // PV: row pr, v-group pc (32 dims)

    float m = -1.0e30f, l = 0.f;
    float acc[32];
#pragma unroll
    for (int i = 0; i < 32; i++) acc[i] = 0.f;

    for (int sb = 0; sb <= qb; sb++) {
        const int s0 = sb * 64;
        // load K (64x192) and V (64x128)
#pragma unroll
        for (int i = 0; i < 12; i++) {
            int idx4 = tid + i * 256;
            int r = idx4 / 48, d4 = idx4 % 48;
            float4 v = *(const float4*)&g_k[(size_t)(h * TT + s0 + r) * DQK + d4 * 4];
            sK[r * QP + d4 * 4 + 0] = v.x;
            sK[r * QP + d4 * 4 + 1] = v.y;
            sK[r * QP + d4 * 4 + 2] = v.z;
            sK[r * QP + d4 * 4 + 3] = v.w;
        }
#pragma unroll
        for (int i = 0; i < 8; i++) {
            int idx4 = tid + i * 256;
            int r = idx4 >> 5, v4 = idx4 & 31;
            *(float4*)&sV[r * DV + v4 * 4] =
                *(const float4*)&g_v[(size_t)(h * TT + s0 + r) * DV + v4 * 4];
        }
        __syncthreads();

        // ---- S = Q K^T (4x4 micro-tile per thread) ----
        float sacc[4][4];
#pragma unroll
        for (int i = 0; i < 4; i++)
#pragma unroll
            for (int j = 0; j < 4; j++) sacc[i][j] = 0.f;

#pragma unroll 4
        for (int d = 0; d < DQK; d++) {
            float q0 = sQ[(ty * 4 + 0) * QP + d];
            float q1 = sQ[(ty * 4 + 1) * QP + d];
            float q2 = sQ[(ty * 4 + 2) * QP + d];
            float q3 = sQ[(ty * 4 + 3) * QP + d];
            float k0v = sK[(tx + 0)  * QP + d];
            float k1v = sK[(tx + 16) * QP + d];
            float k2v = sK[(tx + 32) * QP + d];
            float k3v = sK[(tx + 48) * QP + d];
            sacc[0][0] += q0 * k0v; sacc[0][1] += q0 * k1v; sacc[0][2] += q0 * k2v; sacc[0][3] += q0 * k3v;
            sacc[1][0] += q1 * k0v; sacc[1][1] += q1 * k1v; sacc[1][2] += q1 * k2v; sacc[1][3] += q1 * k3v;
            sacc[2][0] += q2 * k0v; sacc[2][1] += q2 * k1v; sacc[2][2] += q2 * k2v; sacc[2][3] += q2 * k3v;
            sacc[3][0] += q3 * k0v; sacc[3][1] += q3 * k1v; sacc[3][2] += q3 * k2v; sacc[3][3] += q3 * k3v;
        }

        const bool diag = (sb == qb);
#pragma unroll
        for (int i = 0; i < 4; i++) {
#pragma unroll
            for (int j = 0; j < 4; j++) {
                int sl = tx + 16 * j;
                float v = sacc[i][j] * ATT_SCALE;
                if (diag && (s0 + sl > t0 + ty * 4 + i)) v = -1.0e30f;
                sS[(ty * 4 + i) * SP + sl] = v;
            }
        }
        __syncthreads();

        // ---- online softmax (4 threads per row, 16 cols each) ----
        float pm = -1.0e30f;
#pragma unroll
        for (int s = 0; s < 16; s++) pm = fmaxf(pm, sS[pr * SP + pc * 16 + s]);
        pm = fmaxf(pm, __shfl_xor_sync(0xffffffff, pm, 1));
        pm = fmaxf(pm, __shfl_xor_sync(0xffffffff, pm, 2));
        float mnew = fmaxf(m, pm);
        float alpha = __expf(m - mnew);
        float psum = 0.f;
#pragma unroll
        for (int s = 0; s < 16; s++) {
            float p = __expf(sS[pr * SP + pc * 16 + s] - mnew);
            sS[pr * SP + pc * 16 + s] = p;
            psum += p;
        }
        psum += __shfl_xor_sync(0xffffffff, psum, 1);
        psum += __shfl_xor_sync(0xffffffff, psum, 2);
        l = l * alpha + psum;
        m = mnew;
#pragma unroll
        for (int i = 0; i < 32; i++) acc[i] *= alpha;
        __syncthreads();   // p values visible to all 4 threads of the row

        // ---- O += P V ----
        for (int s = 0; s < 64; s++) {
            float p = sS[pr * SP + s];
#pragma unroll
            for (int v4i = 0; v4i < 8; v4i++) {
                float4 vv = *(const float4*)&sV[s * DV + pc * 32 + v4i * 4];
                acc[v4i * 4 + 0] += p * vv.x;
                acc[v4i * 4 + 1] += p * vv.y;
                acc[v4i * 4 + 2] += p * vv.z;
                acc[v4i * 4 + 3] += p * vv.w;
            }
        }
        __syncthreads();   // before K/V/S are overwritten
    }

    const float inv = 1.f / l;
#pragma unroll
    for (int v4i = 0; v4i < 8; v4i++) {
        float4 o = make_float4(acc[v4i * 4 + 0] * inv, acc[v4i * 4 + 1] * inv,
                               acc[v4i * 4 + 2] * inv, acc[v4i * 4 + 3] * inv);
        *(float4*)&out[(size_t)(t0 + pr) * (HH * DV) + h * DV + pc * 32 + v4i * 4] = o;
    }
}

// ---------------------------------------------------------------------------
extern "C" void kernel_launch(void* const* d_in, const int* in_sizes, int n_in,
                              void* d_out, int out_size) {
    const float* q   = (const float*)d_in[0];   // (T, H, 192)
    const float* kc  = (const float*)d_in[1];   // (T, 512)
    const float* kpe = (const float*)d_in[2];   // (T, 64)
    const float* wkv = (const float*)d_in[3];   // (512, 4096)
    const float* wuv = (const float*)d_in[4];   // (H, 512, 128)
    float* out = (float*)d_out;                 // (T, 2048)

    knope_kernel<<<dim3(32, 32), 256>>>(kc, wkv);
    pefill_kernel<<<(HH * TT * DROPE + 255) / 256, 256>>>(kpe);
    vbuild_kernel<<<dim3(2, 32, HH), 256>>>(kc, wuv);

    const int flash_smem = FLASH_SMEM_FLOATS * (int)sizeof(float);
    cudaFuncSetAttribute(flash_kernel, cudaFuncAttributeMaxDynamicSharedMemorySize,
                         flash_smem);
    flash_kernel<<<dim3(32, HH), 256, flash_smem>>>(q, out);
}

// round 4
// speedup vs baseline: 1.6187x; 1.6187x over previous
#include <cuda_runtime.h>
#include <math.h>

#define TT     2048
#define HH     16
#define DQK    192
#define DNOPE  128
#define DROPE  64
#define DLORA  512
#define DV     128
#define ATT_SCALE 0.07216878364870323f   // 1/sqrt(192)

// Scratch (static __device__ — allocation rules forbid cudaMalloc)
__device__ float g_k[HH * TT * DQK];   // (h, t, 192): k_nope | k_pe
__device__ float g_v[HH * TT * DV];    // (h, t, 128): kc @ w_uv[h]

// ---------------------------------------------------------------------------
// Kernel 1: K_nope = kc (2048x512) @ w_kv_b[:, h*256 : h*256+128] -> g_k[..,0:128]
// ---------------------------------------------------------------------------
__global__ __launch_bounds__(256) void knope_kernel(const float* __restrict__ kc,
                                                    const float* __restrict__ wkv) {
    __shared__ float As[16][68];
    __shared__ float Bs[16][68];
    const int tid = threadIdx.x;
    const int m0 = blockIdx.y * 64;
    const int n0 = blockIdx.x * 64;
    const int h = n0 >> 7;
    const int dbase = n0 & 127;
    const int tx = tid & 15, ty = tid >> 4;
    const int am = tid >> 2, ak4 = (tid & 3) * 4;

    float acc[4][4];
#pragma unroll
    for (int i = 0; i < 4; i++)
#pragma unroll
        for (int j = 0; j < 4; j++) acc[i][j] = 0.f;

    for (int k0 = 0; k0 < DLORA; k0 += 16) {
        float4 av = *(const float4*)&kc[(m0 + am) * DLORA + k0 + ak4];
        As[ak4 + 0][am] = av.x;
        As[ak4 + 1][am] = av.y;
        As[ak4 + 2][am] = av.z;
        As[ak4 + 3][am] = av.w;
#pragma unroll
        for (int i = 0; i < 4; i++) {
            int lin = tid + i * 256;
            int kk = lin >> 6, n = lin & 63;
            Bs[kk][n] = wkv[(k0 + kk) * (HH * 256) + h * 256 + dbase + n];
        }
        __syncthreads();
#pragma unroll
        for (int kk = 0; kk < 16; kk++) {
            float4 a = *(const float4*)&As[kk][ty * 4];
            float4 b = *(const float4*)&Bs[kk][tx * 4];
            acc[0][0] += a.x * b.x; acc[0][1] += a.x * b.y; acc[0][2] += a.x * b.z; acc[0][3] += a.x * b.w;
            acc[1][0] += a.y * b.x; acc[1][1] += a.y * b.y; acc[1][2] += a.y * b.z; acc[1][3] += a.y * b.w;
            acc[2][0] += a.z * b.x; acc[2][1] += a.z * b.y; acc[2][2] += a.z * b.z; acc[2][3] += a.z * b.w;
            acc[3][0] += a.w * b.x; acc[3][1] += a.w * b.y; acc[3][2] += a.w * b.z; acc[3][3] += a.w * b.w;
        }
        __syncthreads();
    }
#pragma unroll
    for (int i = 0; i < 4; i++) {
        float4 o = make_float4(acc[i][0], acc[i][1], acc[i][2], acc[i][3]);
        *(float4*)&g_k[(h * TT + m0 + ty * 4 + i) * DQK + dbase + tx * 4] = o;
    }
}

// ---------------------------------------------------------------------------
// Kernel 2: broadcast k_pe into g_k[h][t][128:192]
// ---------------------------------------------------------------------------
__global__ __launch_bounds__(256) void pefill_kernel(const float* __restrict__ kpe) {
    int idx = blockIdx.x * 256 + threadIdx.x;
    if (idx >= HH * TT * DROPE) return;
    int r = idx & 63;
    int t = (idx >> 6) & (TT - 1);
    int h = idx >> 17;
    g_k[(h * TT + t) * DQK + DNOPE + r] = kpe[t * DROPE + r];
}

// ---------------------------------------------------------------------------
// Kernel 3: g_v[h] = kc (2048x512) @ w_uv[h] (512x128)
// ---------------------------------------------------------------------------
__global__ __launch_bounds__(256) void vbuild_kernel(const float* __restrict__ kc,
                                                     const float* __restrict__ wuv) {
    __shared__ float As[16][68];
    __shared__ float Bs[16][68];
    const int tid = threadIdx.x;
    const int m0 = blockIdx.y * 64;
    const int n0 = blockIdx.x * 64;
    const int h = blockIdx.z;
    const int tx = tid & 15, ty = tid >> 4;
    const int am = tid >> 2, ak4 = (tid & 3) * 4;
    const float* wh = wuv + (size_t)h * DLORA * DV;

    float acc[4][4];
#pragma unroll
    for (int i = 0; i < 4; i++)
#pragma unroll
        for (int j = 0; j < 4; j++) acc[i][j] = 0.f;

    for (int k0 = 0; k0 < DLORA; k0 += 16) {
        float4 av = *(const float4*)&kc[(m0 + am) * DLORA + k0 + ak4];
        As[ak4 + 0][am] = av.x;
        As[ak4 + 1][am] = av.y;
        As[ak4 + 2][am] = av.z;
        As[ak4 + 3][am] = av.w;
#pragma unroll
        for (int i = 0; i < 4; i++) {
            int lin = tid + i * 256;
            int kk = lin >> 6, n = lin & 63;
            Bs[kk][n] = wh[(k0 + kk) * DV + n0 + n];
        }
        __syncthreads();
#pragma unroll
        for (int kk = 0; kk < 16; kk++) {
            float4 a = *(const float4*)&As[kk][ty * 4];
            float4 b = *(const float4*)&Bs[kk][tx * 4];
            acc[0][0] += a.x * b.x; acc[0][1] += a.x * b.y; acc[0][2] += a.x * b.z; acc[0][3] += a.x * b.w;
            acc[1][0] += a.y * b.x; acc[1][1] += a.y * b.y; acc[1][2] += a.y * b.z; acc[1][3] += a.y * b.w;
            acc[2][0] += a.z * b.x; acc[2][1] += a.z * b.y; acc[2][2] += a.z * b.z; acc[2][3] += a.z * b.w;
            acc[3][0] += a.w * b.x; acc[3][1] += a.w * b.y; acc[3][2] += a.w * b.z; acc[3][3] += a.w * b.w;
        }
        __syncthreads();
    }
#pragma unroll
    for (int i = 0; i < 4; i++) {
        float4 o = make_float4(acc[i][0], acc[i][1], acc[i][2], acc[i][3]);
        *(float4*)&g_v[(h * TT + m0 + ty * 4 + i) * DV + n0 + tx * 4] = o;
    }
}

// ---------------------------------------------------------------------------
// Kernel 4: causal flash attention, 64x64 tiles, vectorized 128-bit smem ops
// ---------------------------------------------------------------------------
#define QP 196   // multiple of 4 (float4-aligned rows); 196%32=4 -> 2-way floor on K reads
#define SP 68
#define FLASH_SMEM_FLOATS (2 * 64 * QP + 64 * DV + 64 * SP + 3 * 64)

__global__ __launch_bounds__(256, 1) void flash_kernel(const float* __restrict__ q,
                                                       float* __restrict__ out) {
    extern __shared__ float sm[];
    float* sQ = sm;                       // 64 x QP
    float* sK = sQ + 64 * QP;             // 64 x QP
    float* sV = sK + 64 * QP;             // 64 x 128
    float* sS = sV + 64 * DV;             // 64 x SP
    float* sM = sS + 64 * SP;             // 64 (running row max)
    float* sL = sM + 64;                  // 64 (running row sum)
    float* sA = sL + 64;                  // 64 (per-tile alpha)

    const int tid = threadIdx.x;
    const int h = blockIdx.y;
    const int qb = (gridDim.x - 1) - blockIdx.x;   // heavy blocks first
    const int t0 = qb * 64;

    // per-row softmax state init
    if (tid < 64) { sM[tid] = -1.0e30f; sL[tid] = 0.f; }
    __syncthreads();

    // load Q tile (64 x 192)
#pragma unroll
    for (int i = 0; i < 12; i++) {
        int idx4 = tid + i * 256;
        int r = idx4 / 48, d4 = idx4 % 48;
        *(float4*)&sQ[r * QP + d4 * 4] =
            *(const float4*)&q[(size_t)(t0 + r) * (HH * DQK) + h * DQK + d4 * 4];
    }

    // S-phase map: rows ty*4+i, cols tx+16j
    const int tx = tid & 15, ty = tid >> 4;
    // softmax map: row smr, 16-col group smc
    const int smr = tid >> 2, smc = tid & 3;
    // PV map: rows pvr and pvr+32, v-dims pvc..pvc+15
    const int pvr = tid >> 3, pvc = (tid & 7) * 16;

    float accA[16], accB[16];
#pragma unroll
    for (int i = 0; i < 16; i++) { accA[i] = 0.f; accB[i] = 0.f; }

    for (int sb = 0; sb <= qb; sb++) {
        const int s0 = sb * 64;
        // load K (64x192) and V (64x128)
#pragma unroll
        for (int i = 0; i < 12; i++) {
            int idx4 = tid + i * 256;
            int r = idx4 / 48, d4 = idx4 % 48;
            *(float4*)&sK[r * QP + d4 * 4] =
                *(const float4*)&g_k[(size_t)(h * TT + s0 + r) * DQK + d4 * 4];
        }
#pragma unroll
        for (int i = 0; i < 8; i++) {
            int idx4 = tid + i * 256;
            int r = idx4 >> 5, v4 = idx4 & 31;
            *(float4*)&sV[r * DV + v4 * 4] =
                *(const float4*)&g_v[(size_t)(h * TT + s0 + r) * DV + v4 * 4];
        }
        __syncthreads();

        // ---- S = Q K^T : float4 over d, 4x4 micro-tile ----
        float sacc[4][4];
#pragma unroll
        for (int i = 0; i < 4; i++)
#pragma unroll
            for (int j = 0; j < 4; j++) sacc[i][j] = 0.f;

#pragma unroll 2
        for (int d = 0; d < DQK; d += 4) {
            float4 qv[4], kv[4];
#pragma unroll
            for (int i = 0; i < 4; i++) qv[i] = *(const float4*)&sQ[(ty * 4 + i) * QP + d];
#pragma unroll
            for (int j = 0; j < 4; j++) kv[j] = *(const float4*)&sK[(tx + 16 * j) * QP + d];
#pragma unroll
            for (int i = 0; i < 4; i++)
#pragma unroll
                for (int j = 0; j < 4; j++) {
                    sacc[i][j] += qv[i].x * kv[j].x;
                    sacc[i][j] += qv[i].y * kv[j].y;
                    sacc[i][j] += qv[i].z * kv[j].z;
                    sacc[i][j] += qv[i].w * kv[j].w;
                }
        }

        const bool diag = (sb == qb);
#pragma unroll
        for (int i = 0; i < 4; i++) {
#pragma unroll
            for (int j = 0; j < 4; j++) {
                int sl = tx + 16 * j;
                float v = sacc[i][j] * ATT_SCALE;
                if (diag && (s0 + sl > t0 + ty * 4 + i)) v = -1.0e30f;
                sS[(ty * 4 + i) * SP + sl] = v;
            }
        }
        __syncthreads();

        // ---- online softmax: 4 threads per row, float4 ----
        {
            float4 v0 = *(const float4*)&sS[smr * SP + smc * 16 + 0];
            float4 v1 = *(const float4*)&sS[smr * SP + smc * 16 + 4];
            float4 v2 = *(const float4*)&sS[smr * SP + smc * 16 + 8];
            float4 v3 = *(const float4*)&sS[smr * SP + smc * 16 + 12];
            float pm = fmaxf(fmaxf(fmaxf(v0.x, v0.y), fmaxf(v0.z, v0.w)),
                             fmaxf(fmaxf(v1.x, v1.y), fmaxf(v1.z, v1.w)));
            pm = fmaxf(pm, fmaxf(fmaxf(fmaxf(v2.x, v2.y), fmaxf(v2.z, v2.w)),
                                 fmaxf(fmaxf(v3.x, v3.y), fmaxf(v3.z, v3.w))));
            pm = fmaxf(pm, __shfl_xor_sync(0xffffffff, pm, 1));
            pm = fmaxf(pm, __shfl_xor_sync(0xffffffff, pm, 2));
            float mold = sM[smr];
            float mnew = fmaxf(mold, pm);
            float alpha = __expf(mold - mnew);
            v0.x = __expf(v0.x - mnew); v0.y = __expf(v0.y - mnew);
            v0.z = __expf(v0.z - mnew); v0.w = __expf(v0.w - mnew);
            v1.x = __expf(v1.x - mnew); v1.y = __expf(v1.y - mnew);
            v1.z = __expf(v1.z - mnew); v1.w = __expf(v1.w - mnew);
            v2.x = __expf(v2.x - mnew); v2.y = __expf(v2.y - mnew);
            v2.z = __expf(v2.z - mnew); v2.w = __expf(v2.w - mnew);
            v3.x = __expf(v3.x - mnew); v3.y = __expf(v3.y - mnew);
            v3.z = __expf(v3.z - mnew); v3.w = __expf(v3.w - mnew);
            *(float4*)&sS[smr * SP + smc * 16 + 0]  = v0;
            *(float4*)&sS[smr * SP + smc * 16 + 4]  = v1;
            *(float4*)&sS[smr * SP + smc * 16 + 8]  = v2;
            *(float4*)&sS[smr * SP + smc * 16 + 12] = v3;
            float psum = v0.x + v0.y + v0.z + v0.w + v1.x + v1.y + v1.z + v1.w
                       + v2.x + v2.y + v2.z + v2.w + v3.x + v3.y + v3.z + v3.w;
            psum += __shfl_xor_sync(0xffffffff, psum, 1);
            psum += __shfl_xor_sync(0xffffffff, psum, 2);
            if (smc == 0) {
                sL[smr] = sL[smr] * alpha + psum;
                sM[smr] = mnew;
                sA[smr] = alpha;
            }
        }
        __syncthreads();

        // ---- O += P V : 2 rows x 16 dims per thread, float4 ----
        {
            float aA = sA[pvr];
            float aB = sA[pvr + 32];
#pragma unroll
            for (int i = 0; i < 16; i++) { accA[i] *= aA; accB[i] *= aB; }
        }
#pragma unroll 2
        for (int s4 = 0; s4 < 16; s4++) {
            float4 pA = *(const float4*)&sS[pvr * SP + s4 * 4];
            float4 pB = *(const float4*)&sS[(pvr + 32) * SP + s4 * 4];
            float pa[4] = {pA.x, pA.y, pA.z, pA.w};
            float pb[4] = {pB.x, pB.y, pB.z, pB.w};
#pragma unroll
            for (int k = 0; k < 4; k++) {
                int s = s4 * 4 + k;
#pragma unroll
                for (int v4 = 0; v4 < 4; v4++) {
                    float4 vv = *(const float4*)&sV[s * DV + pvc + v4 * 4];
                    accA[v4 * 4 + 0] += pa[k] * vv.x;
                    accA[v4 * 4 + 1] += pa[k] * vv.y;
                    accA[v4 * 4 + 2] += pa[k] * vv.z;
                    accA[v4 * 4 + 3] += pa[k] * vv.w;
                    accB[v4 * 4 + 0] += pb[k] * vv.x;
                    accB[v4 * 4 + 1] += pb[k] * vv.y;
                    accB[v4 * 4 + 2] += pb[k] * vv.z;
                    accB[v4 * 4 + 3] += pb[k] * vv.w;
                }
            }
        }
        __syncthreads();   // before K/V/S overwritten next iter
    }

    const float invA = 1.f / sL[pvr];
    const float invB = 1.f / sL[pvr + 32];
#pragma unroll
    for (int v4 = 0; v4 < 4; v4++) {
        float4 oA = make_float4(accA[v4 * 4 + 0] * invA, accA[v4 * 4 + 1] * invA,
                                accA[v4 * 4 + 2] * invA, accA[v4 * 4 + 3] * invA);
        float4 oB = make_float4(accB[v4 * 4 + 0] * invB, accB[v4 * 4 + 1] * invB,
                                accB[v4 * 4 + 2] * invB, accB[v4 * 4 + 3] * invB);
        *(float4*)&out[(size_t)(t0 + pvr) * (HH * DV) + h * DV + pvc + v4 * 4] = oA;
        *(float4*)&out[(size_t)(t0 + pvr + 32) * (HH * DV) + h * DV + pvc + v4 * 4] = oB;
    }
}

// ---------------------------------------------------------------------------
extern "C" void kernel_launch(void* const* d_in, const int* in_sizes, int n_in,
                              void* d_out, int out_size) {
    const float* q   = (const float*)d_in[0];   // (T, H, 192)
    const float* kc  = (const float*)d_in[1];   // (T, 512)
    const float* kpe = (const float*)d_in[2];   // (T, 64)
    const float* wkv = (const float*)d_in[3];   // (512, 4096)
    const float* wuv = (const float*)d_in[4];   // (H, 512, 128)
    float* out = (float*)d_out;                 // (T, 2048)

    knope_kernel<<<dim3(32, 32), 256>>>(kc, wkv);
    pefill_kernel<<<(HH * TT * DROPE + 255) / 256, 256>>>(kpe);
    vbuild_kernel<<<dim3(2, 32, HH), 256>>>(kc, wuv);

    const int flash_smem = FLASH_SMEM_FLOATS * (int)sizeof(float);
    cudaFuncSetAttribute(flash_kernel, cudaFuncAttributeMaxDynamicSharedMemorySize,
                         flash_smem);
    flash_kernel<<<dim3(32, HH), 256, flash_smem>>>(q, out);
}

// round 5
// speedup vs baseline: 3.9829x; 2.4606x over previous
#include <cuda_runtime.h>
#include <math.h>

#define TT     2048
#define HH     16
#define DQK    192
#define DNOPE  128
#define DROPE  64
#define DLORA  512
#define DV     128
#define ATT_SCALE 0.07216878364870323f   // 1/sqrt(192)

// Scratch (static __device__ — allocation rules forbid cudaMalloc)
__device__ float g_k[HH * TT * DQK];   // (h, t, 192): k_nope | k_pe
__device__ float g_v[HH * TT * DV];    // (h, t, 128): kc @ w_uv[h]

// ---------------------------------------------------------------------------
// Kernel 1: K_nope = kc (2048x512) @ w_kv_b[:, h*256 : h*256+128]
// 128x128 tile, 8x8 micro-tile, k-step 16
// ---------------------------------------------------------------------------
__global__ __launch_bounds__(256) void knope_kernel(const float* __restrict__ kc,
                                                    const float* __restrict__ wkv) {
    __shared__ float As[16][132];
    __shared__ float Bs[16][132];
    const int tid = threadIdx.x;
    const int h  = blockIdx.x;
    const int m0 = blockIdx.y * 128;
    const int tx = tid & 15, ty = tid >> 4;
    const int am = tid >> 2, ak4 = (tid & 3) * 4;

    float acc[8][8];
#pragma unroll
    for (int i = 0; i < 8; i++)
#pragma unroll
        for (int j = 0; j < 8; j++) acc[i][j] = 0.f;

    for (int k0 = 0; k0 < DLORA; k0 += 16) {
#pragma unroll
        for (int ii = 0; ii < 2; ii++) {
            int m = am + ii * 64;
            float4 av = *(const float4*)&kc[(size_t)(m0 + m) * DLORA + k0 + ak4];
            As[ak4 + 0][m] = av.x;
            As[ak4 + 1][m] = av.y;
            As[ak4 + 2][m] = av.z;
            As[ak4 + 3][m] = av.w;
        }
#pragma unroll
        for (int i = 0; i < 2; i++) {
            int lin = tid + i * 256;
            int kk = lin >> 5, n4 = (lin & 31) * 4;
            *(float4*)&Bs[kk][n4] =
                *(const float4*)&wkv[(size_t)(k0 + kk) * (HH * 256) + h * 256 + n4];
        }
        __syncthreads();
#pragma unroll
        for (int kk = 0; kk < 16; kk++) {
            float4 a0 = *(const float4*)&As[kk][ty * 8];
            float4 a1 = *(const float4*)&As[kk][ty * 8 + 4];
            float4 b0 = *(const float4*)&Bs[kk][tx * 8];
            float4 b1 = *(const float4*)&Bs[kk][tx * 8 + 4];
            float a[8] = {a0.x, a0.y, a0.z, a0.w, a1.x, a1.y, a1.z, a1.w};
            float b[8] = {b0.x, b0.y, b0.z, b0.w, b1.x, b1.y, b1.z, b1.w};
#pragma unroll
            for (int i = 0; i < 8; i++)
#pragma unroll
                for (int j = 0; j < 8; j++) acc[i][j] += a[i] * b[j];
        }
        __syncthreads();
    }
#pragma unroll
    for (int i = 0; i < 8; i++) {
        float4 o0 = make_float4(acc[i][0], acc[i][1], acc[i][2], acc[i][3]);
        float4 o1 = make_float4(acc[i][4], acc[i][5], acc[i][6], acc[i][7]);
        size_t base = (size_t)(h * TT + m0 + ty * 8 + i) * DQK + tx * 8;
        *(float4*)&g_k[base]     = o0;
        *(float4*)&g_k[base + 4] = o1;
    }
}

// ---------------------------------------------------------------------------
// Kernel 2: broadcast k_pe into g_k[h][t][128:192]
// ---------------------------------------------------------------------------
__global__ __launch_bounds__(256) void pefill_kernel(const float* __restrict__ kpe) {
    int idx = blockIdx.x * 256 + threadIdx.x;
    if (idx >= HH * TT * DROPE) return;
    int r = idx & 63;
    int t = (idx >> 6) & (TT - 1);
    int h = idx >> 17;
    g_k[(h * TT + t) * DQK + DNOPE + r] = kpe[t * DROPE + r];
}

// ---------------------------------------------------------------------------
// Kernel 3: g_v[h] = kc (2048x512) @ w_uv[h] (512x128), 128x128 tiles, 8x8 micro
// ---------------------------------------------------------------------------
__global__ __launch_bounds__(256) void vbuild_kernel(const float* __restrict__ kc,
                                                     const float* __restrict__ wuv) {
    __shared__ float As[16][132];
    __shared__ float Bs[16][132];
    const int tid = threadIdx.x;
    const int h  = blockIdx.x;
    const int m0 = blockIdx.y * 128;
    const int tx = tid & 15, ty = tid >> 4;
    const int am = tid >> 2, ak4 = (tid & 3) * 4;
    const float* wh = wuv + (size_t)h * DLORA * DV;

    float acc[8][8];
#pragma unroll
    for (int i = 0; i < 8; i++)
#pragma unroll
        for (int j = 0; j < 8; j++) acc[i][j] = 0.f;

    for (int k0 = 0; k0 < DLORA; k0 += 16) {
#pragma unroll
        for (int ii = 0; ii < 2; ii++) {
            int m = am + ii * 64;
            float4 av = *(const float4*)&kc[(size_t)(m0 + m) * DLORA + k0 + ak4];
            As[ak4 + 0][m] = av.x;
            As[ak4 + 1][m] = av.y;
            As[ak4 + 2][m] = av.z;
            As[ak4 + 3][m] = av.w;
        }
#pragma unroll
        for (int i = 0; i < 2; i++) {
            int lin = tid + i * 256;
            int kk = lin >> 5, n4 = (lin & 31) * 4;
            *(float4*)&Bs[kk][n4] = *(const float4*)&wh[(size_t)(k0 + kk) * DV + n4];
        }
        __syncthreads();
#pragma unroll
        for (int kk = 0; kk < 16; kk++) {
            float4 a0 = *(const float4*)&As[kk][ty * 8];
            float4 a1 = *(const float4*)&As[kk][ty * 8 + 4];
            float4 b0 = *(const float4*)&Bs[kk][tx * 8];
            float4 b1 = *(const float4*)&Bs[kk][tx * 8 + 4];
            float a[8] = {a0.x, a0.y, a0.z, a0.w, a1.x, a1.y, a1.z, a1.w};
            float b[8] = {b0.x, b0.y, b0.z, b0.w, b1.x, b1.y, b1.z, b1.w};
#pragma unroll
            for (int i = 0; i < 8; i++)
#pragma unroll
                for (int j = 0; j < 8; j++) acc[i][j] += a[i] * b[j];
        }
        __syncthreads();
    }
#pragma unroll
    for (int i = 0; i < 8; i++) {
        float4 o0 = make_float4(acc[i][0], acc[i][1], acc[i][2], acc[i][3]);
        float4 o1 = make_float4(acc[i][4], acc[i][5], acc[i][6], acc[i][7]);
        size_t base = (size_t)(h * TT + m0 + ty * 8 + i) * DV + tx * 8;
        *(float4*)&g_v[base]     = o0;
        *(float4*)&g_v[base + 4] = o1;
    }
}

// ---------------------------------------------------------------------------
// Kernel 4: causal flash attention, 128x128 tiles, 8x8 micro S-phase,
// d chunked by 64, register-resident S accumulators, 1 CTA/SM
// ---------------------------------------------------------------------------
#define CP  68    // d-chunk row stride (64 + 4 pad; 68%32=4 -> conflict-free strided)
#define SPP 132   // S row stride
#define FLASH_SMEM_FLOATS (2 * 128 * CP + 128 * DV + 128 * SPP + 3 * 128)

__global__ __launch_bounds__(256, 1) void flash_kernel(const float* __restrict__ q,
                                                       float* __restrict__ out) {
    extern __shared__ float sm[];
    float* sQ = sm;                        // 128 x CP  (d-chunk)
    float* sK = sQ + 128 * CP;             // 128 x CP
    float* sV = sK + 128 * CP;             // 128 x 128
    float* sS = sV + 128 * DV;             // 128 x SPP
    float* sM = sS + 128 * SPP;            // 128
    float* sL = sM + 128;                  // 128
    float* sA = sL + 128;                  // 128

    const int tid = threadIdx.x;
    const int id = blockIdx.x;
    const int h  = id & 15;
    const int qb = 15 - (id >> 4);         // heaviest q-blocks first
    const int t0 = qb * 128;

    if (tid < 128) { sM[tid] = -1.0e30f; sL[tid] = 0.f; }

    const int tx = tid & 15, ty = tid >> 4;    // S map: rows ty+16i, cols tx+16j
    const int smr = tid >> 1, smc = tid & 1;   // softmax: row smr, half smc
    const int pvr = tid >> 3;                  // PV rows pvr+32k
    const int pvc = (tid & 7) * 4;             // PV v-dims pvc + 32*v4 (+0..3)

    float acc[4][16];
#pragma unroll
    for (int k = 0; k < 4; k++)
#pragma unroll
        for (int u = 0; u < 16; u++) acc[k][u] = 0.f;

    for (int sb = 0; sb <= qb; sb++) {
        const int s0 = sb * 128;

        float sacc[8][8];
#pragma unroll
        for (int i = 0; i < 8; i++)
#pragma unroll
            for (int j = 0; j < 8; j++) sacc[i][j] = 0.f;

        // ---- S = Q K^T over 3 d-chunks of 64 ----
        for (int c = 0; c < 3; c++) {
            const int c0 = c * 64;
#pragma unroll
            for (int i = 0; i < 8; i++) {
                int idx4 = tid + i * 256;
                int r = idx4 >> 4, d4 = (idx4 & 15) * 4;
                *(float4*)&sQ[r * CP + d4] =
                    *(const float4*)&q[(size_t)(t0 + r) * (HH * DQK) + h * DQK + c0 + d4];
                *(float4*)&sK[r * CP + d4] =
                    *(const float4*)&g_k[(size_t)(h * TT + s0 + r) * DQK + c0 + d4];
            }
            if (c == 0) {
#pragma unroll
                for (int i = 0; i < 16; i++) {
                    int idx4 = tid + i * 256;
                    int r = idx4 >> 5, v4 = (idx4 & 31) * 4;
                    *(float4*)&sV[r * DV + v4] =
                        *(const float4*)&g_v[(size_t)(h * TT + s0 + r) * DV + v4];
                }
            }
            __syncthreads();

#pragma unroll 2
            for (int d = 0; d < 64; d += 4) {
                float4 kv[8];
#pragma unroll
                for (int j = 0; j < 8; j++) kv[j] = *(const float4*)&sK[(tx + 16 * j) * CP + d];
#pragma unroll
                for (int i = 0; i < 8; i++) {
                    float4 qv = *(const float4*)&sQ[(ty + 16 * i) * CP + d];
#pragma unroll
                    for (int j = 0; j < 8; j++) {
                        sacc[i][j] += qv.x * kv[j].x;
                        sacc[i][j] += qv.y * kv[j].y;
                        sacc[i][j] += qv.z * kv[j].z;
                        sacc[i][j] += qv.w * kv[j].w;
                    }
                }
            }
            __syncthreads();
        }

        // ---- mask + scale + store S ----
        const bool diag = (sb == qb);
#pragma unroll
        for (int i = 0; i < 8; i++) {
            int row = ty + 16 * i;
#pragma unroll
            for (int j = 0; j < 8; j++) {
                int col = tx + 16 * j;
                float v = sacc[i][j] * ATT_SCALE;
                if (diag && col > row) v = -1.0e30f;   // s0 == t0 on diagonal tile
                sS[row * SPP + col] = v;
            }
        }
        __syncthreads();

        // ---- online softmax: 2 threads per row, 64 cols each ----
        {
            const int b = smr * SPP + smc * 64;
            float4 vv[16];
            float pm = -1.0e30f;
#pragma unroll
            for (int t = 0; t < 16; t++) {
                vv[t] = *(const float4*)&sS[b + t * 4];
                pm = fmaxf(pm, fmaxf(fmaxf(vv[t].x, vv[t].y), fmaxf(vv[t].z, vv[t].w)));
            }
            pm = fmaxf(pm, __shfl_xor_sync(0xffffffff, pm, 1));
            float mold = sM[smr];
            float mnew = fmaxf(mold, pm);
            float alpha = __expf(mold - mnew);
            float psum = 0.f;
#pragma unroll
            for (int t = 0; t < 16; t++) {
                vv[t].x = __expf(vv[t].x - mnew);
                vv[t].y = __expf(vv[t].y - mnew);
                vv[t].z = __expf(vv[t].z - mnew);
                vv[t].w = __expf(vv[t].w - mnew);
                *(float4*)&sS[b + t * 4] = vv[t];
                psum += vv[t].x + vv[t].y + vv[t].z + vv[t].w;
            }
            psum += __shfl_xor_sync(0xffffffff, psum, 1);
            if (smc == 0) {
                sL[smr] = sL[smr] * alpha + psum;
                sM[smr] = mnew;
                sA[smr] = alpha;
            }
        }
        __syncthreads();

        // ---- O += P V : 4 rows x 16 v-dims per thread ----
        {
            float a0 = sA[pvr], a1 = sA[pvr + 32], a2 = sA[pvr + 64], a3 = sA[pvr + 96];
#pragma unroll
            for (int u = 0; u < 16; u++) {
                acc[0][u] *= a0; acc[1][u] *= a1; acc[2][u] *= a2; acc[3][u] *= a3;
            }
        }
#pragma unroll 2
        for (int s4 = 0; s4 < 32; s4++) {
            float4 p0 = *(const float4*)&sS[(pvr +  0) * SPP + s4 * 4];
            float4 p1 = *(const float4*)&sS[(pvr + 32) * SPP + s4 * 4];
            float4 p2 = *(const float4*)&sS[(pvr + 64) * SPP + s4 * 4];
            float4 p3 = *(const float4*)&sS[(pvr + 96) * SPP + s4 * 4];
            float pr0[4] = {p0.x, p0.y, p0.z, p0.w};
            float pr1[4] = {p1.x, p1.y, p1.z, p1.w};
            float pr2[4] = {p2.x, p2.y, p2.z, p2.w};
            float pr3[4] = {p3.x, p3.y, p3.z, p3.w};
#pragma unroll
            for (int jj = 0; jj < 4; jj++) {
                int s = s4 * 4 + jj;
#pragma unroll
                for (int v4 = 0; v4 < 4; v4++) {
                    float4 vv = *(const float4*)&sV[s * DV + pvc + v4 * 32];
                    acc[0][v4 * 4 + 0] += pr0[jj] * vv.x;
                    acc[0][v4 * 4 + 1] += pr0[jj] * vv.y;
                    acc[0][v4 * 4 + 2] += pr0[jj] * vv.z;
                    acc[0][v4 * 4 + 3] += pr0[jj] * vv.w;
                    acc[1][v4 * 4 + 0] += pr1[jj] * vv.x;
                    acc[1][v4 * 4 + 1] += pr1[jj] * vv.y;
                    acc[1][v4 * 4 + 2] += pr1[jj] * vv.z;
                    acc[1][v4 * 4 + 3] += pr1[jj] * vv.w;
                    acc[2][v4 * 4 + 0] += pr2[jj] * vv.x;
                    acc[2][v4 * 4 + 1] += pr2[jj] * vv.y;
                    acc[2][v4 * 4 + 2] += pr2[jj] * vv.z;
                    acc[2][v4 * 4 + 3] += pr2[jj] * vv.w;
                    acc[3][v4 * 4 + 0] += pr3[jj] * vv.x;
                    acc[3][v4 * 4 + 1] += pr3[jj] * vv.y;
                    acc[3][v4 * 4 + 2] += pr3[jj] * vv.z;
                    acc[3][v4 * 4 + 3] += pr3[jj] * vv.w;
                }
            }
        }
        __syncthreads();   // before sQ/sK/sV/sS overwritten next tile-step
    }

    // ---- epilogue: normalize + store ----
#pragma unroll
    for (int k = 0; k < 4; k++) {
        int row = pvr + 32 * k;
        float inv = 1.f / sL[row];
#pragma unroll
        for (int v4 = 0; v4 < 4; v4++) {
            float4 o = make_float4(acc[k][v4 * 4 + 0] * inv, acc[k][v4 * 4 + 1] * inv,
                                   acc[k][v4 * 4 + 2] * inv, acc[k][v4 * 4 + 3] * inv);
            *(float4*)&out[(size_t)(t0 + row) * (HH * DV) + h * DV + pvc + v4 * 32] = o;
        }
    }
}

// ---------------------------------------------------------------------------
extern "C" void kernel_launch(void* const* d_in, const int* in_sizes, int n_in,
                              void* d_out, int out_size) {
    const float* q   = (const float*)d_in[0];   // (T, H, 192)
    const float* kc  = (const float*)d_in[1];   // (T, 512)
    const float* kpe = (const float*)d_in[2];   // (T, 64)
    const float* wkv = (const float*)d_in[3];   // (512, 4096)
    const float* wuv = (const float*)d_in[4];   // (H, 512, 128)
    float* out = (float*)d_out;                 // (T, 2048)

    knope_kernel<<<dim3(16, 16), 256>>>(kc, wkv);
    pefill_kernel<<<(HH * TT * DROPE + 255) / 256, 256>>>(kpe);
    vbuild_kernel<<<dim3(16, 16), 256>>>(kc, wuv);

    const int flash_smem = FLASH_SMEM_FLOATS * (int)sizeof(float);
    cudaFuncSetAttribute(flash_kernel, cudaFuncAttributeMaxDynamicSharedMemorySize,
                         flash_smem);
    flash_kernel<<<256, 256, flash_smem>>>(q, out);
}

// round 7
// speedup vs baseline: 6.5270x; 1.6388x over previous
#include <cuda_runtime.h>
#include <cuda_fp16.h>
#include <math.h>
#include <stdint.h>

#define TT     2048
#define HH     16
#define DQK    192
#define DNOPE  128
#define DROPE  64
#define DLORA  512
#define DV     128
#define ATT_SCALE 0.07216878364870323f   // 1/sqrt(192)

// ---------------- scratch (static __device__; no cudaMalloc allowed) --------
__device__ float  g_v[HH * TT * DV];           // fp32 (h,t,128)
__device__ __half g_qh[HH * TT * DQK];         // fp16 hi (h,t,192)
__device__ __half g_ql[HH * TT * DQK];         // fp16 lo
__device__ __half g_kh[HH * TT * DQK];
__device__ __half g_kl[HH * TT * DQK];
__device__ __half g_vth[HH * DV * TT];         // fp16 hi V^T (h,v,t)

// ---------------------------------------------------------------------------
// helpers
// ---------------------------------------------------------------------------
__device__ __forceinline__ void split2pack(float x, float y, uint32_t& hi, uint32_t& lo) {
    __half hx = __float2half_rn(x), hy = __float2half_rn(y);
    __half lx = __float2half_rn(x - __half2float(hx));
    __half ly = __float2half_rn(y - __half2float(hy));
    hi = (uint32_t)__half_as_ushort(hx) | ((uint32_t)__half_as_ushort(hy) << 16);
    lo = (uint32_t)__half_as_ushort(lx) | ((uint32_t)__half_as_ushort(ly) << 16);
}

__device__ __forceinline__ void mma16816(float* d, const uint32_t* a, const uint32_t* b) {
    asm volatile(
        "mma.sync.aligned.m16n8k16.row.col.f32.f16.f16.f32 "
        "{%0,%1,%2,%3}, {%4,%5,%6,%7}, {%8,%9}, {%0,%1,%2,%3};"
        : "+f"(d[0]), "+f"(d[1]), "+f"(d[2]), "+f"(d[3])
        : "r"(a[0]), "r"(a[1]), "r"(a[2]), "r"(a[3]), "r"(b[0]), "r"(b[1]));
}

// ---------------------------------------------------------------------------
// Kernel 1: K_nope = kc @ w_kv_b[:, h*256 : h*256+128] -> g_kh/g_kl (fp16 split)
// ---------------------------------------------------------------------------
__global__ __launch_bounds__(256) void knope_kernel(const float* __restrict__ kc,
                                                    const float* __restrict__ wkv) {
    __shared__ float As[16][132];
    __shared__ float Bs[16][132];
    const int tid = threadIdx.x;
    const int h  = blockIdx.x;
    const int m0 = blockIdx.y * 128;
    const int tx = tid & 15, ty = tid >> 4;
    const int am = tid >> 2, ak4 = (tid & 3) * 4;

    float acc[8][8];
#pragma unroll
    for (int i = 0; i < 8; i++)
#pragma unroll
        for (int j = 0; j < 8; j++) acc[i][j] = 0.f;

    for (int k0 = 0; k0 < DLORA; k0 += 16) {
#pragma unroll
        for (int ii = 0; ii < 2; ii++) {
            int m = am + ii * 64;
            float4 av = *(const float4*)&kc[(size_t)(m0 + m) * DLORA + k0 + ak4];
            As[ak4 + 0][m] = av.x;
            As[ak4 + 1][m] = av.y;
            As[ak4 + 2][m] = av.z;
            As[ak4 + 3][m] = av.w;
        }
#pragma unroll
        for (int i = 0; i < 2; i++) {
            int lin = tid + i * 256;
            int kk = lin >> 5, n4 = (lin & 31) * 4;
            *(float4*)&Bs[kk][n4] =
                *(const float4*)&wkv[(size_t)(k0 + kk) * (HH * 256) + h * 256 + n4];
        }
        __syncthreads();
#pragma unroll
        for (int kk = 0; kk < 16; kk++) {
            float4 a0 = *(const float4*)&As[kk][ty * 8];
            float4 a1 = *(const float4*)&As[kk][ty * 8 + 4];
            float4 b0 = *(const float4*)&Bs[kk][tx * 8];
            float4 b1 = *(const float4*)&Bs[kk][tx * 8 + 4];
            float a[8] = {a0.x, a0.y, a0.z, a0.w, a1.x, a1.y, a1.z, a1.w};
            float b[8] = {b0.x, b0.y, b0.z, b0.w, b1.x, b1.y, b1.z, b1.w};
#pragma unroll
            for (int i = 0; i < 8; i++)
#pragma unroll
                for (int j = 0; j < 8; j++) acc[i][j] += a[i] * b[j];
        }
        __syncthreads();
    }
#pragma unroll
    for (int i = 0; i < 8; i++) {
        uint32_t ph[4], pl[4];
#pragma unroll
        for (int j = 0; j < 4; j++)
            split2pack(acc[i][2 * j], acc[i][2 * j + 1], ph[j], pl[j]);
        size_t base = (size_t)(h * TT + m0 + ty * 8 + i) * DQK + tx * 8;
        *(uint4*)&g_kh[base] = make_uint4(ph[0], ph[1], ph[2], ph[3]);
        *(uint4*)&g_kl[base] = make_uint4(pl[0], pl[1], pl[2], pl[3]);
    }
}

// ---------------------------------------------------------------------------
// Kernel 2: broadcast k_pe (split) into g_kh/g_kl[h][t][128:192]
// ---------------------------------------------------------------------------
__global__ __launch_bounds__(256) void pefill_kernel(const float* __restrict__ kpe) {
    int idx = blockIdx.x * 256 + threadIdx.x;
    if (idx >= HH * TT * DROPE) return;
    int r = idx & 63;
    int t = (idx >> 6) & (TT - 1);
    int h = idx >> 17;
    float x = kpe[t * DROPE + r];
    __half hx = __float2half_rn(x);
    __half lx = __float2half_rn(x - __half2float(hx));
    size_t o = (size_t)(h * TT + t) * DQK + DNOPE + r;
    g_kh[o] = hx;
    g_kl[o] = lx;
}

// ---------------------------------------------------------------------------
// Kernel 3: g_v[h] = kc @ w_uv[h]  (fp32, 128x128, 8x8)
// ---------------------------------------------------------------------------
__global__ __launch_bounds__(256) void vbuild_kernel(const float* __restrict__ kc,
                                                     const float* __restrict__ wuv) {
    __shared__ float As[16][132];
    __shared__ float Bs[16][132];
    const int tid = threadIdx.x;
    const int h  = blockIdx.x;
    const int m0 = blockIdx.y * 128;
    const int tx = tid & 15, ty = tid >> 4;
    const int am = tid >> 2, ak4 = (tid & 3) * 4;
    const float* wh = wuv + (size_t)h * DLORA * DV;

    float acc[8][8];
#pragma unroll
    for (int i = 0; i < 8; i++)
#pragma unroll
        for (int j = 0; j < 8; j++) acc[i][j] = 0.f;

    for (int k0 = 0; k0 < DLORA; k0 += 16) {
#pragma unroll
        for (int ii = 0; ii < 2; ii++) {
            int m = am + ii * 64;
            float4 av = *(const float4*)&kc[(size_t)(m0 + m) * DLORA + k0 + ak4];
            As[ak4 + 0][m] = av.x;
            As[ak4 + 1][m] = av.y;
            As[ak4 + 2][m] = av.z;
            As[ak4 + 3][m] = av.w;
        }
#pragma unroll
        for (int i = 0; i < 2; i++) {
            int lin = tid + i * 256;
            int kk = lin >> 5, n4 = (lin & 31) * 4;
            *(float4*)&Bs[kk][n4] = *(const float4*)&wh[(size_t)(k0 + kk) * DV + n4];
        }
        __syncthreads();
#pragma unroll
        for (int kk = 0; kk < 16; kk++) {
            float4 a0 = *(const float4*)&As[kk][ty * 8];
            float4 a1 = *(const float4*)&As[kk][ty * 8 + 4];
            float4 b0 = *(const float4*)&Bs[kk][tx * 8];
            float4 b1 = *(const float4*)&Bs[kk][tx * 8 + 4];
            float a[8] = {a0.x, a0.y, a0.z, a0.w, a1.x, a1.y, a1.z, a1.w};
            float b[8] = {b0.x, b0.y, b0.z, b0.w, b1.x, b1.y, b1.z, b1.w};
#pragma unroll
            for (int i = 0; i < 8; i++)
#pragma unroll
                for (int j = 0; j < 8; j++) acc[i][j] += a[i] * b[j];
        }
        __syncthreads();
    }
#pragma unroll
    for (int i = 0; i < 8; i++) {
        float4 o0 = make_float4(acc[i][0], acc[i][1], acc[i][2], acc[i][3]);
        float4 o1 = make_float4(acc[i][4], acc[i][5], acc[i][6], acc[i][7]);
        size_t base = (size_t)(h * TT + m0 + ty * 8 + i) * DV + tx * 8;
        *(float4*)&g_v[base]     = o0;
        *(float4*)&g_v[base + 4] = o1;
    }
}

// ---------------------------------------------------------------------------
// Kernel 4: q (t,h,192) fp32 -> g_qh/g_ql (h,t,192) fp16
// ---------------------------------------------------------------------------
__global__ __launch_bounds__(256) void qsplit_kernel(const float* __restrict__ q) {
    int g = blockIdx.x * 256 + threadIdx.x;   // over elems/8
    int u = g % 24;
    int th = g / 24;
    int h = th & 15;
    int t = th >> 4;
    int d8 = u * 8;
    float4 a = *(const float4*)&q[(size_t)(t * HH + h) * DQK + d8];
    float4 b = *(const float4*)&q[(size_t)(t * HH + h) * DQK + d8 + 4];
    float x[8] = {a.x, a.y, a.z, a.w, b.x, b.y, b.z, b.w};
    uint32_t ph[4], pl[4];
#pragma unroll
    for (int j = 0; j < 4; j++) split2pack(x[2 * j], x[2 * j + 1], ph[j], pl[j]);
    size_t o = (size_t)(h * TT + t) * DQK + d8;
    *(uint4*)&g_qh[o] = make_uint4(ph[0], ph[1], ph[2], ph[3]);
    *(uint4*)&g_ql[o] = make_uint4(pl[0], pl[1], pl[2], pl[3]);
}

// ---------------------------------------------------------------------------
// Kernel 5: g_v (h,t,128) -> g_vth (h,v,t) fp16 hi, 64x64 transpose tiles
// ---------------------------------------------------------------------------
__global__ __launch_bounds__(256) void vtsplit_kernel() {
    __shared__ float ts[64][65];
    const int tid = threadIdx.x;
    const int tb = blockIdx.x * 64;
    const int vb = blockIdx.y * 64;
    const int h  = blockIdx.z;
#pragma unroll
    for (int i = 0; i < 16; i++) {
        int idx = tid + i * 256;
        int tt = idx >> 6, vv = idx & 63;
        ts[tt][vv] = g_v[(size_t)(h * TT + tb + tt) * DV + vb + vv];
    }
    __syncthreads();
#pragma unroll
    for (int i = 0; i < 16; i++) {
        int idx = tid + i * 256;
        int vv = idx >> 6, tt = idx & 63;
        g_vth[(size_t)(h * DV + vb + vv) * TT + tb + tt] = __float2half_rn(ts[tt][vv]);
    }
}

// ---------------------------------------------------------------------------
// Kernel 6: flash attention on mma.sync (HMMA). q-tile 128, k-tile 64.
// QK = QhKh + QlKh + QhKl; PV = (Ph + Pl) * Vh. FA2 register dataflow.
// SMEM holds fragment-ready operands (lane-indexed, conflict-free).
// ---------------------------------------------------------------------------
// u32-index SMEM bases:  Q [12ch][8mt][32ln][4]  K [12ch][8nt][32ln][2]
//                        V [4ch][16nt][32ln][2]
#define SQH 0
#define SQL 12288
#define SKH 24576
#define SKL 30720
#define SVH 36864
#define FLASH_SMEM_BYTES (40960 * 4)

__global__ __launch_bounds__(256, 1) void flash_mma_kernel(float* __restrict__ out) {
    extern __shared__ uint32_t smw[];
    const int tid = threadIdx.x;
    const int w = tid >> 5, lane = tid & 31;
    const int gr = lane >> 2, tg = lane & 3;
    const int id = blockIdx.x;
    const int h = id & 15, qb = 15 - (id >> 4);   // heaviest q-tiles first
    const int t0 = qb * 128;
    const int nsteps = 2 * qb + 2;

    // ---- stage Q fragments (once per CTA) ----
#pragma unroll
    for (int i = 0; i < 12; i++) {
        int idx = tid + i * 256;
        int rr = idx / 24, u = idx % 24;
        int ch = u >> 1, kk0 = (u & 1) << 3;
        int mt = rr >> 4, r16 = rr & 15;
        int lw = (r16 & 7) << 2;
        int reg = ((kk0 >> 3) << 1) | (r16 >> 3);
        size_t go = (size_t)(h * TT + t0 + rr) * DQK + ch * 16 + kk0;
        uint4 vh = *(const uint4*)&g_qh[go];
        uint4 vl = *(const uint4*)&g_ql[go];
        uint32_t bi = (uint32_t)(((ch * 8 + mt) * 32 + lw) * 4 + reg);
        smw[SQH + bi] = vh.x; smw[SQH + bi + 4] = vh.y;
        smw[SQH + bi + 8] = vh.z; smw[SQH + bi + 12] = vh.w;
        smw[SQL + bi] = vl.x; smw[SQL + bi + 4] = vl.y;
        smw[SQL + bi + 8] = vl.z; smw[SQL + bi + 12] = vl.w;
    }

    float mA = -1.0e30f, mB = -1.0e30f, lA = 0.f, lB = 0.f;
    float O[16][4];
#pragma unroll
    for (int n = 0; n < 16; n++)
#pragma unroll
        for (int e = 0; e < 4; e++) O[n][e] = 0.f;

    for (int sb = 0; sb < nsteps; sb++) {
        const int s0 = sb * 64;
        __syncthreads();   // previous step's fragment reads complete

        // ---- stage K hi/lo fragments ----
#pragma unroll
        for (int i = 0; i < 6; i++) {
            int idx = tid + i * 256;
            int sr = idx / 24, u = idx % 24;
            int ch = u >> 1, kk0 = (u & 1) << 3;
            int nt = sr >> 3, lw = (sr & 7) << 2;
            int reg = kk0 >> 3;
            size_t go = (size_t)(h * TT + s0 + sr) * DQK + ch * 16 + kk0;
            uint4 vh = *(const uint4*)&g_kh[go];
            uint4 vl = *(const uint4*)&g_kl[go];
            uint32_t bi = (uint32_t)(((ch * 8 + nt) * 32 + lw) * 2 + reg);
            smw[SKH + bi] = vh.x; smw[SKH + bi + 2] = vh.y;
            smw[SKH + bi + 4] = vh.z; smw[SKH + bi + 6] = vh.w;
            smw[SKL + bi] = vl.x; smw[SKL + bi + 2] = vl.y;
            smw[SKL + bi + 4] = vl.z; smw[SKL + bi + 6] = vl.w;
        }
        // ---- stage V hi fragments ----
#pragma unroll
        for (int i = 0; i < 4; i++) {
            int idx = tid + i * 256;
            int v = idx >> 3, u = idx & 7;
            int ch = u >> 1, kk0 = (u & 1) << 3;
            int nt = v >> 3, lw = (v & 7) << 2;
            int reg = kk0 >> 3;
            size_t go = (size_t)(h * DV + v) * TT + s0 + ch * 16 + kk0;
            uint4 vv = *(const uint4*)&g_vth[go];
            uint32_t bi = (uint32_t)(((ch * 16 + nt) * 32 + lw) * 2 + reg);
            smw[SVH + bi] = vv.x; smw[SVH + bi + 2] = vv.y;
            smw[SVH + bi + 4] = vv.z; smw[SVH + bi + 6] = vv.w;
        }
        __syncthreads();

        if (s0 > t0 + w * 16 + 15) continue;   // warp tile fully masked

        // ---- S = Q K^T ----
        float S[8][4];
#pragma unroll
        for (int n = 0; n < 8; n++)
#pragma unroll
            for (int e = 0; e < 4; e++) S[n][e] = 0.f;

#pragma unroll 1
        for (int ch = 0; ch < 12; ch++) {
            uint32_t ab = (uint32_t)(((ch * 8 + w) * 32 + lane) * 4);
            uint4 aH4 = *(const uint4*)&smw[SQH + ab];
            uint4 aL4 = *(const uint4*)&smw[SQL + ab];
            uint32_t aH[4] = {aH4.x, aH4.y, aH4.z, aH4.w};
            uint32_t aL[4] = {aL4.x, aL4.y, aL4.z, aL4.w};
#pragma unroll
            for (int nt = 0; nt < 8; nt++) {
                uint32_t kb = (uint32_t)(((ch * 8 + nt) * 32 + lane) * 2);
                uint2 bH = *(const uint2*)&smw[SKH + kb];
                uint32_t bh[2] = {bH.x, bH.y};
                mma16816(S[nt], aH, bh);
                mma16816(S[nt], aL, bh);
                uint2 bL = *(const uint2*)&smw[SKL + kb];
                uint32_t bl[2] = {bL.x, bL.y};
                mma16816(S[nt], aH, bl);
            }
        }

        // ---- scale + causal mask ----
        const int rowA = t0 + w * 16 + gr;
        const bool msk = (s0 + 63 > rowA);
#pragma unroll
        for (int nt = 0; nt < 8; nt++) {
            int col = s0 + nt * 8 + 2 * tg;
#pragma unroll
            for (int e = 0; e < 2; e++) {
                float xA = S[nt][e] * ATT_SCALE;
                float xB = S[nt][2 + e] * ATT_SCALE;
                if (msk) {
                    if (col + e > rowA) xA = -1.0e30f;
                    if (col + e > rowA + 8) xB = -1.0e30f;
                }
                S[nt][e] = xA;
                S[nt][2 + e] = xB;
            }
        }

        // ---- online softmax (rows gr and gr+8; reduce over lane%4) ----
        float pmA = -1.0e30f, pmB = -1.0e30f;
#pragma unroll
        for (int nt = 0; nt < 8; nt++) {
            pmA = fmaxf(pmA, fmaxf(S[nt][0], S[nt][1]));
            pmB = fmaxf(pmB, fmaxf(S[nt][2], S[nt][3]));
        }
        pmA = fmaxf(pmA, __shfl_xor_sync(0xffffffffu, pmA, 1));
        pmA = fmaxf(pmA, __shfl_xor_sync(0xffffffffu, pmA, 2));
        pmB = fmaxf(pmB, __shfl_xor_sync(0xffffffffu, pmB, 1));
        pmB = fmaxf(pmB, __shfl_xor_sync(0xffffffffu, pmB, 2));
        float mnA = fmaxf(mA, pmA), mnB = fmaxf(mB, pmB);
        float aAf = __expf(mA - mnA), aBf = __expf(mB - mnB);
        float sA = 0.f, sB = 0.f;
#pragma unroll
        for (int nt = 0; nt < 8; nt++) {
            S[nt][0] = __expf(S[nt][0] - mnA);
            S[nt][1] = __expf(S[nt][1] - mnA);
            S[nt][2] = __expf(S[nt][2] - mnB);
            S[nt][3] = __expf(S[nt][3] - mnB);
            sA += S[nt][0] + S[nt][1];
            sB += S[nt][2] + S[nt][3];
        }
        sA += __shfl_xor_sync(0xffffffffu, sA, 1);
        sA += __shfl_xor_sync(0xffffffffu, sA, 2);
        sB += __shfl_xor_sync(0xffffffffu, sB, 1);
        sB += __shfl_xor_sync(0xffffffffu, sB, 2);
        lA = lA * aAf + sA; mA = mnA;
        lB = lB * aBf + sB; mB = mnB;
#pragma unroll
        for (int n = 0; n < 16; n++) {
            O[n][0] *= aAf; O[n][1] *= aAf;
            O[n][2] *= aBf; O[n][3] *= aBf;
        }

        // ---- O += P V : P from S-regs via C-frag->A-frag repack ----
#pragma unroll 1
        for (int c = 0; c < 4; c++) {
            uint32_t aPh[4], aPl[4];
#pragma unroll
            for (int q2 = 0; q2 < 2; q2++)
#pragma unroll
                for (int pr = 0; pr < 2; pr++)
                    split2pack(S[2 * c + q2][pr * 2], S[2 * c + q2][pr * 2 + 1],
                               aPh[q2 * 2 + pr], aPl[q2 * 2 + pr]);
#pragma unroll
            for (int nt = 0; nt < 16; nt++) {
                uint32_t vb = (uint32_t)(((c * 16 + nt) * 32 + lane) * 2);
                uint2 bV = *(const uint2*)&smw[SVH + vb];
                uint32_t b2[2] = {bV.x, bV.y};
                mma16816(O[nt], aPh, b2);
                mma16816(O[nt], aPl, b2);
            }
        }
    }

    // ---- epilogue ----
    const float iA = 1.f / lA, iB = 1.f / lB;
    const int rowA = t0 + w * 16 + gr;
#pragma unroll
    for (int nt = 0; nt < 16; nt++) {
        int col = h * DV + nt * 8 + 2 * tg;
        *(float2*)&out[(size_t)rowA * (HH * DV) + col] =
            make_float2(O[nt][0] * iA, O[nt][1] * iA);
        *(float2*)&out[(size_t)(rowA + 8) * (HH * DV) + col] =
            make_float2(O[nt][2] * iB, O[nt][3] * iB);
    }
}

// ---------------------------------------------------------------------------
extern "C" void kernel_launch(void* const* d_in, const int* in_sizes, int n_in,
                              void* d_out, int out_size) {
    const float* q   = (const float*)d_in[0];   // (T, H, 192)
    const float* kc  = (const float*)d_in[1];   // (T, 512)
    const float* kpe = (const float*)d_in[2];   // (T, 64)
    const float* wkv = (const float*)d_in[3];   // (512, 4096)
    const float* wuv = (const float*)d_in[4];   // (H, 512, 128)
    float* out = (float*)d_out;                 // (T, 2048)

    knope_kernel<<<dim3(16, 16), 256>>>(kc, wkv);
    pefill_kernel<<<(HH * TT * DROPE + 255) / 256, 256>>>(kpe);
    vbuild_kernel<<<dim3(16, 16), 256>>>(kc, wuv);
    vtsplit_kernel<<<dim3(32, 2, 16), 256>>>();
    qsplit_kernel<<<HH * TT * DQK / 8 / 256, 256>>>(q);

    cudaFuncSetAttribute(flash_mma_kernel, cudaFuncAttributeMaxDynamicSharedMemorySize,
                         FLASH_SMEM_BYTES);
    flash_mma_kernel<<<256, 256, FLASH_SMEM_BYTES>>>(out);
}